// round 17
// speedup vs baseline: 7.6730x; 1.0152x over previous
#include <cuda_runtime.h>
#include <cuda_fp16.h>
#include <math.h>
#include <stdint.h>

#define NTOK 4096
#define DIM 768
#define DEPTH 6
#define HEADS 12
#define DH 64
#define FF 3072
#define MF 256
#define VOCAB 102
#define DNORM 0.35355339059327373f   /* 64^-0.25 */
#define RATIO 0.0625f                /* 256^-0.5 */
#define L2E 1.4426950408889634f
#define NZS 16                        /* ctx n-splits */

// per-layer half-weight offsets (in halves)
#define LOFF 7077888
#define WOQ 0
#define WOK 589824
#define WOV 1179648
#define WOO 1769472
#define WO1 2359296
#define WO2 4718592

// ---------------- scratch (device globals, no allocation) ----------------
__device__ float g_x[NTOK * DIM];
__device__ __align__(16) __half g_hh[NTOK * DIM];
__device__ float g_q[NTOK * DIM];
__device__ float g_k[NTOK * DIM];
__device__ float g_v[NTOK * DIM];
__device__ __align__(16) __half g_attnh[NTOK * DIM];
__device__ __align__(16) __half g_ffh[NTOK * FF];
__device__ __align__(16) __half g_wh[(size_t)DEPTH * LOFF];
__device__ __align__(16) __half g_woh[128 * DIM];          // Wout^T half, padded
__device__ __align__(16) __half g_qf[HEADS * NTOK * MF];   // raw xd (half)
__device__ __align__(16) __half g_kf[HEADS * NTOK * MF];   // raw xd (half)
__device__ float g_diagq[HEADS * NTOK];
__device__ float g_diagk[HEADS * NTOK];
__device__ float g_maxq2[2 * HEADS * NTOK];
__device__ float g_maxk2[HEADS * 64];
__device__ float g_ksum[HEADS * MF];
__device__ float g_ctx[HEADS * MF * DH];
__device__ float g_ctxp[NZS * HEADS * MF * DH];
__device__ float g_ksump[NZS * HEADS * MF];

// ---------------- helpers ----------------
__device__ __forceinline__ float tanh_fast(float x) {
    float r;
    asm("tanh.approx.f32 %0, %1;" : "=f"(r) : "f"(x));
    return r;
}

__device__ __forceinline__ float ex2f(float y) {
    float r;
    asm("ex2.approx.f32 %0, %1;" : "=f"(r) : "f"(y));
    return r;
}

__device__ __forceinline__ float gelu_tanh(float u) {
    return 0.5f * u * (1.0f + tanh_fast(0.7978845608028654f * (u + 0.044715f * u * u * u)));
}

__device__ __forceinline__ uint32_t to_tf32u(float x) {
    float r;
    asm("cvt.rna.tf32.f32 %0, %1;" : "=f"(r) : "f"(x));
    return __float_as_uint(r);
}

__device__ __forceinline__ void mma8(float* c, const uint32_t* a, const uint32_t* b) {
    asm volatile(
        "mma.sync.aligned.m16n8k8.row.col.f32.tf32.tf32.f32 "
        "{%0,%1,%2,%3}, {%4,%5,%6,%7}, {%8,%9}, {%0,%1,%2,%3};"
        : "+f"(c[0]), "+f"(c[1]), "+f"(c[2]), "+f"(c[3])
        : "r"(a[0]), "r"(a[1]), "r"(a[2]), "r"(a[3]), "r"(b[0]), "r"(b[1]));
}

__device__ __forceinline__ void mma16(float* c, const uint32_t* a, const uint32_t* b) {
    asm volatile(
        "mma.sync.aligned.m16n8k16.row.col.f32.f16.f16.f32 "
        "{%0,%1,%2,%3}, {%4,%5,%6,%7}, {%8,%9}, {%0,%1,%2,%3};"
        : "+f"(c[0]), "+f"(c[1]), "+f"(c[2]), "+f"(c[3])
        : "r"(a[0]), "r"(a[1]), "r"(a[2]), "r"(a[3]), "r"(b[0]), "r"(b[1]));
}

__device__ __forceinline__ void ldsm4(uint32_t* r, uint32_t addr) {
    asm volatile("ldmatrix.sync.aligned.m8n8.x4.shared.b16 {%0,%1,%2,%3}, [%4];"
        : "=r"(r[0]), "=r"(r[1]), "=r"(r[2]), "=r"(r[3]) : "r"(addr));
}

__device__ __forceinline__ void cp_async16(uint32_t dst, const void* src) {
    asm volatile("cp.async.cg.shared.global [%0], [%1], 16;" :: "r"(dst), "l"(src));
}
__device__ __forceinline__ void cp_commit() { asm volatile("cp.async.commit_group;"); }
__device__ __forceinline__ void cp_wait1() { asm volatile("cp.async.wait_group 1;"); }
__device__ __forceinline__ void cp_wait0() { asm volatile("cp.async.wait_group 0;"); }

// ---------------- weight convert + transpose helpers ----------------------
__device__ __forceinline__ void wtile_transpose(const float* src, __half* dst,
                                                int K, int N, int k0, int n0) {
    __shared__ float tile[32][33];
    int tx = threadIdx.x & 31, ty = threadIdx.x >> 5;   // 32x8
    #pragma unroll
    for (int i = 0; i < 4; i++)
        tile[ty + i * 8][tx] = src[(size_t)(k0 + ty + i * 8) * N + n0 + tx];
    __syncthreads();
    #pragma unroll
    for (int i = 0; i < 4; i++)
        dst[(size_t)(n0 + ty + i * 8) * K + k0 + tx] = __float2half(tile[tx][ty + i * 8]);
}

__global__ __launch_bounds__(256) void wconv_sq(const float* __restrict__ Wq,
                                                const float* __restrict__ Wk,
                                                const float* __restrict__ Wv,
                                                const float* __restrict__ Wo) {
    int zz = blockIdx.z, l = zz >> 2, mat = zz & 3;
    const float* srcs[4] = {Wq, Wk, Wv, Wo};
    const size_t offs[4] = {WOQ, WOK, WOV, WOO};
    wtile_transpose(srcs[mat] + (size_t)l * DIM * DIM,
                    g_wh + (size_t)l * LOFF + offs[mat],
                    DIM, DIM, blockIdx.y * 32, blockIdx.x * 32);
}

__global__ __launch_bounds__(256) void wconv_ff(const float* __restrict__ W1,
                                                const float* __restrict__ W2) {
    int l = blockIdx.y, mat = blockIdx.z, f = blockIdx.x;
    int K, N, n0, k0;
    size_t off;
    const float* src;
    if (mat == 0) { K = DIM; N = FF;  n0 = (f % 96) * 32; k0 = (f / 96) * 32; off = WO1; src = W1; }
    else          { K = FF;  N = DIM; n0 = (f % 24) * 32; k0 = (f / 24) * 32; off = WO2; src = W2; }
    wtile_transpose(src + (size_t)l * K * N,
                    g_wh + (size_t)l * LOFF + off, K, N, k0, n0);
}

// Wout [768][102] fp32 -> g_woh [128][768] half (padded rows zero)
__global__ __launch_bounds__(256) void wconv_out(const float* __restrict__ Wout) {
    int i = blockIdx.x * 256 + threadIdx.x;
    if (i >= 128 * DIM) return;
    int n = i / DIM, k = i - n * DIM;
    float v = (n < VOCAB) ? Wout[(size_t)k * VOCAB + n] : 0.f;
    g_woh[(size_t)n * DIM + k] = __float2half(v);
}

// ---------------- embedding + bucketize ----------------
__global__ void embed_kernel(const float* __restrict__ methy,
                             const int* __restrict__ chromo,
                             const int* __restrict__ pos,
                             const float* __restrict__ mt,
                             const float* __restrict__ ct,
                             const float* __restrict__ pt) {
    int n = blockIdx.x;
    float x = methy[n];
    int idx = (x > -2.0f) + (x > -1.0f);
    #pragma unroll 4
    for (int i = 0; i < 100; i++) idx += ((float)i * 0.01f < x) ? 1 : 0;
    int c = chromo[n], p = pos[n];
    const float* mrow = mt + (size_t)idx * DIM;
    const float* prow = pt + (size_t)p * DIM;
    const float* crow = ct + (size_t)c * DIM;
    for (int d = threadIdx.x; d < DIM; d += blockDim.x)
        g_x[n * DIM + d] = mrow[d] + prow[d] + crow[d];
}

// ---------------- layernorm: 2 rows/block, 384 thr, float4, shfl ----------
__global__ __launch_bounds__(384) void ln_kernel(const float* __restrict__ in,
                                                 const float* __restrict__ g,
                                                 const float* __restrict__ b,
                                                 __half* __restrict__ outh) {
    int t = threadIdx.x;
    int half_id = t >= 192;
    int n = blockIdx.x * 2 + half_id;
    int tl = t - half_id * 192;
    int lane = t & 31, wid = t >> 5;
    __shared__ float ws[12], ws2[12];
    float4 v = *(const float4*)&in[(size_t)n * DIM + tl * 4];
    float s = v.x + v.y + v.z + v.w;
    for (int off = 16; off; off >>= 1) s += __shfl_xor_sync(0xffffffffu, s, off);
    if (lane == 0) ws[wid] = s;
    __syncthreads();
    int wb = half_id * 6;
    float mu = (ws[wb] + ws[wb+1] + ws[wb+2] + ws[wb+3] + ws[wb+4] + ws[wb+5]) * (1.0f / DIM);
    float dx = v.x - mu, dy = v.y - mu, dz = v.z - mu, dw = v.w - mu;
    float s2 = dx * dx + dy * dy + dz * dz + dw * dw;
    for (int off = 16; off; off >>= 1) s2 += __shfl_xor_sync(0xffffffffu, s2, off);
    if (lane == 0) ws2[wid] = s2;
    __syncthreads();
    float rstd = rsqrtf((ws2[wb] + ws2[wb+1] + ws2[wb+2] + ws2[wb+3] + ws2[wb+4] + ws2[wb+5]) * (1.0f / DIM) + 1e-5f);
    float4 gg = *(const float4*)&g[tl * 4];
    float4 bb = *(const float4*)&b[tl * 4];
    float4 o;
    o.x = dx * rstd * gg.x + bb.x;
    o.y = dy * rstd * gg.y + bb.y;
    o.z = dz * rstd * gg.z + bb.z;
    o.w = dw * rstd * gg.w + bb.w;
    *(__half2*)&outh[(size_t)n * DIM + tl * 4] = __floats2half2_rn(o.x, o.y);
    *(__half2*)&outh[(size_t)n * DIM + tl * 4 + 2] = __floats2half2_rn(o.z, o.w);
}

// ---------------- FP16 GEMM 128x128x64h, cp.async 3-stage, ldmatrix -------
#define BKH 64
#define SAH 72
#define HAELE (128 * SAH)
#define HSTAGES 3

__global__ __launch_bounds__(256, 2) void tgemm_h(const __half* __restrict__ A,
                                                  const __half* __restrict__ B0,
                                                  const __half* __restrict__ B1,
                                                  const __half* __restrict__ B2,
                                                  const float* __restrict__ bias,
                                                  float* __restrict__ C0,
                                                  float* __restrict__ C1,
                                                  float* __restrict__ C2,
                                                  int Nn, int Kk, int act, int splitk,
                                                  int outhalf) {
    extern __shared__ __half hsm[];
    int z = blockIdx.z;
    const __half* B = B0;
    float* C = C0;
    int koff = 0, Keff = Kk;
    if (splitk > 1) {
        Keff = Kk / splitk;
        koff = z * Keff;
    } else {
        B = (z == 0) ? B0 : ((z == 1) ? B1 : B2);
        C = (z == 0) ? C0 : ((z == 1) ? C1 : C2);
    }

    int t = threadIdx.x;
    int rb = blockIdx.y * 128, cb = blockIdx.x * 128;
    int lane = t & 31, wid = t >> 5;
    int warp_m = (wid & 1) * 64, warp_n = (wid >> 1) * 32;
    int q = lane & 3, g = lane >> 2;

    int tr = t >> 3;
    int tc = (t & 7) * 8;

    const __half* Abase = A + (size_t)(rb + tr) * Kk + koff + tc;
    const __half* Bbase = B + (size_t)(cb + tr) * Kk + koff + tc;

    uint32_t smA = (uint32_t)__cvta_generic_to_shared(hsm);
    uint32_t smB = smA + HSTAGES * HAELE * 2;
    uint32_t adst = smA + (uint32_t)((tr * SAH + tc) * 2);
    uint32_t bdst = smB + (uint32_t)((tr * SAH + tc) * 2);

    uint32_t aoff[4], boff[2];
    {
        int r = (lane & 7) + ((lane >> 3) & 1) * 8;
        int kh = (lane >> 4) * 8;
        #pragma unroll
        for (int mt = 0; mt < 4; mt++)
            aoff[mt] = (uint32_t)(((warp_m + mt * 16 + r) * SAH + kh) * 2);
        int rn = lane & 7;
        int khb = ((lane >> 3) & 1) * 8;
        int pb = lane >> 4;
        #pragma unroll
        for (int p = 0; p < 2; p++)
            boff[p] = (uint32_t)(((warp_n + (p * 2 + pb) * 8 + rn) * SAH + khb) * 2);
    }

    int niter = Keff / BKH;

    #pragma unroll
    for (int s = 0; s < 2; s++) {
        if (s < niter) {
            size_t k0 = (size_t)s * BKH;
            #pragma unroll
            for (int i = 0; i < 4; i++)
                cp_async16(adst + (uint32_t)(s * HAELE * 2 + i * 32 * SAH * 2),
                           Abase + (size_t)(32 * i) * Kk + k0);
            #pragma unroll
            for (int i = 0; i < 4; i++)
                cp_async16(bdst + (uint32_t)(s * HAELE * 2 + i * 32 * SAH * 2),
                           Bbase + (size_t)(32 * i) * Kk + k0);
        }
        cp_commit();
    }

    float acc[4][4][4];
    #pragma unroll
    for (int mt = 0; mt < 4; mt++)
        #pragma unroll
        for (int nt = 0; nt < 4; nt++)
            #pragma unroll
            for (int e = 0; e < 4; e++) acc[mt][nt][e] = 0.f;

    for (int it = 0; it < niter; it++) {
        if (it + 1 < niter) cp_wait1(); else cp_wait0();
        __syncthreads();
        if (it + 2 < niter) {
            int s = (it + 2) % HSTAGES;
            size_t k0 = (size_t)(it + 2) * BKH;
            #pragma unroll
            for (int i = 0; i < 4; i++)
                cp_async16(adst + (uint32_t)(s * HAELE * 2 + i * 32 * SAH * 2),
                           Abase + (size_t)(32 * i) * Kk + k0);
            #pragma unroll
            for (int i = 0; i < 4; i++)
                cp_async16(bdst + (uint32_t)(s * HAELE * 2 + i * 32 * SAH * 2),
                           Bbase + (size_t)(32 * i) * Kk + k0);
        }
        cp_commit();

        uint32_t sa = smA + (uint32_t)((it % HSTAGES) * HAELE * 2);
        uint32_t sb = smB + (uint32_t)((it % HSTAGES) * HAELE * 2);
        #pragma unroll
        for (int ks = 0; ks < 4; ks++) {
            uint32_t kbyte = (uint32_t)(ks * 32);
            uint32_t af[4][4], bfr[2][4];
            #pragma unroll
            for (int mt = 0; mt < 4; mt++) ldsm4(af[mt], sa + aoff[mt] + kbyte);
            #pragma unroll
            for (int p = 0; p < 2; p++) ldsm4(bfr[p], sb + boff[p] + kbyte);
            #pragma unroll
            for (int mt = 0; mt < 4; mt++)
                #pragma unroll
                for (int nt = 0; nt < 4; nt++)
                    mma16(acc[mt][nt], af[mt], &bfr[nt >> 1][(nt & 1) * 2]);
        }
    }
    __syncthreads();

    // epilogue
    if (splitk > 1) {
        #pragma unroll
        for (int mt = 0; mt < 4; mt++)
            #pragma unroll
            for (int nt = 0; nt < 4; nt++)
                #pragma unroll
                for (int e = 0; e < 4; e++) {
                    int row = rb + warp_m + mt * 16 + g + (e >> 1) * 8;
                    int col = cb + warp_n + nt * 8 + q * 2 + (e & 1);
                    float val = acc[mt][nt][e];
                    if (bias && z == 0) val += bias[col];
                    atomicAdd(&C[(size_t)row * Nn + col], val);
                }
    } else {
        #pragma unroll
        for (int mt = 0; mt < 4; mt++)
            #pragma unroll
            for (int nt = 0; nt < 4; nt++)
                #pragma unroll
                for (int eh = 0; eh < 2; eh++) {
                    int row = rb + warp_m + mt * 16 + g + eh * 8;
                    int col = cb + warp_n + nt * 8 + q * 2;
                    float v0 = acc[mt][nt][eh * 2];
                    float v1 = acc[mt][nt][eh * 2 + 1];
                    if (bias) { v0 += bias[col]; v1 += bias[col + 1]; }
                    if (act) { v0 = gelu_tanh(v0); v1 = gelu_tanh(v1); }
                    if (outhalf)
                        *(__half2*)&((__half*)C)[(size_t)row * Nn + col] = __floats2half2_rn(v0, v1);
                    else
                        *(float2*)&C[(size_t)row * Nn + col] = make_float2(v0, v1);
                }
    }
}

// ---------------- output head GEMM: out[4096,102] = hh @ WoutT^T + bout ---
__global__ __launch_bounds__(256, 2) void woutgemm_kernel(const __half* __restrict__ A,
                                                          const float* __restrict__ bout,
                                                          float* __restrict__ out) {
    extern __shared__ __half hsm[];
    int t = threadIdx.x;
    int rb = blockIdx.x * 128;
    int lane = t & 31, wid = t >> 5;
    int warp_m = (wid & 1) * 64, warp_n = (wid >> 1) * 32;
    int q = lane & 3, g = lane >> 2;

    int tr = t >> 3;
    int tc = (t & 7) * 8;

    const __half* Abase = A + (size_t)(rb + tr) * DIM + tc;
    const __half* Bbase = g_woh + (size_t)tr * DIM + tc;

    uint32_t smA = (uint32_t)__cvta_generic_to_shared(hsm);
    uint32_t smB = smA + HSTAGES * HAELE * 2;
    uint32_t adst = smA + (uint32_t)((tr * SAH + tc) * 2);
    uint32_t bdst = smB + (uint32_t)((tr * SAH + tc) * 2);

    uint32_t aoff[4], boff[2];
    {
        int r = (lane & 7) + ((lane >> 3) & 1) * 8;
        int kh = (lane >> 4) * 8;
        #pragma unroll
        for (int mt = 0; mt < 4; mt++)
            aoff[mt] = (uint32_t)(((warp_m + mt * 16 + r) * SAH + kh) * 2);
        int rn = lane & 7;
        int khb = ((lane >> 3) & 1) * 8;
        int pb = lane >> 4;
        #pragma unroll
        for (int p = 0; p < 2; p++)
            boff[p] = (uint32_t)(((warp_n + (p * 2 + pb) * 8 + rn) * SAH + khb) * 2);
    }

    const int niter = DIM / BKH;   // 12

    #pragma unroll
    for (int s = 0; s < 2; s++) {
        size_t k0 = (size_t)s * BKH;
        #pragma unroll
        for (int i = 0; i < 4; i++)
            cp_async16(adst + (uint32_t)(s * HAELE * 2 + i * 32 * SAH * 2),
                       Abase + (size_t)(32 * i) * DIM + k0);
        #pragma unroll
        for (int i = 0; i < 4; i++)
            cp_async16(bdst + (uint32_t)(s * HAELE * 2 + i * 32 * SAH * 2),
                       Bbase + (size_t)(32 * i) * DIM + k0);
        cp_commit();
    }

    float acc[4][4][4];
    #pragma unroll
    for (int mt = 0; mt < 4; mt++)
        #pragma unroll
        for (int nt = 0; nt < 4; nt++)
            #pragma unroll
            for (int e = 0; e < 4; e++) acc[mt][nt][e] = 0.f;

    for (int it = 0; it < niter; it++) {
        if (it + 1 < niter) cp_wait1(); else cp_wait0();
        __syncthreads();
        if (it + 2 < niter) {
            int s = (it + 2) % HSTAGES;
            size_t k0 = (size_t)(it + 2) * BKH;
            #pragma unroll
            for (int i = 0; i < 4; i++)
                cp_async16(adst + (uint32_t)(s * HAELE * 2 + i * 32 * SAH * 2),
                           Abase + (size_t)(32 * i) * DIM + k0);
            #pragma unroll
            for (int i = 0; i < 4; i++)
                cp_async16(bdst + (uint32_t)(s * HAELE * 2 + i * 32 * SAH * 2),
                           Bbase + (size_t)(32 * i) * DIM + k0);
        }
        cp_commit();

        uint32_t sa = smA + (uint32_t)((it % HSTAGES) * HAELE * 2);
        uint32_t sb = smB + (uint32_t)((it % HSTAGES) * HAELE * 2);
        #pragma unroll
        for (int ks = 0; ks < 4; ks++) {
            uint32_t kbyte = (uint32_t)(ks * 32);
            uint32_t af[4][4], bfr[2][4];
            #pragma unroll
            for (int mt = 0; mt < 4; mt++) ldsm4(af[mt], sa + aoff[mt] + kbyte);
            #pragma unroll
            for (int p = 0; p < 2; p++) ldsm4(bfr[p], sb + boff[p] + kbyte);
            #pragma unroll
            for (int mt = 0; mt < 4; mt++)
                #pragma unroll
                for (int nt = 0; nt < 4; nt++)
                    mma16(acc[mt][nt], af[mt], &bfr[nt >> 1][(nt & 1) * 2]);
        }
    }
    __syncthreads();

    #pragma unroll
    for (int mt = 0; mt < 4; mt++)
        #pragma unroll
        for (int nt = 0; nt < 4; nt++)
            #pragma unroll
            for (int eh = 0; eh < 2; eh++) {
                int row = rb + warp_m + mt * 16 + g + eh * 8;
                int col = warp_n + nt * 8 + q * 2;
                if (col < VOCAB) {
                    float v0 = acc[mt][nt][eh * 2] + bout[col];
                    float v1 = acc[mt][nt][eh * 2 + 1] + bout[col + 1];
                    *(float2*)&out[(size_t)row * VOCAB + col] = make_float2(v0, v1);
                }
            }
}

// ---------------- feature GEMM fp16 (half xd output) ----------------------
#define FSH 72
__global__ __launch_bounds__(256, 2) void featgemm_kernel(const float* __restrict__ proj) {
    __shared__ __half As[128 * FSH];
    __shared__ __half Bs[128 * FSH];
    __shared__ float diagacc[128];
    __shared__ float wred[8];
    __shared__ float redq[4][128];
    int hk = blockIdx.z, h = hk >> 1, isK = hk & 1;
    const float* X = isK ? g_k : g_q;
    __half* dst = isK ? g_kf : g_qf;
    int n0 = blockIdx.y * 128, m0 = blockIdx.x * 128;
    int t = threadIdx.x, lane = t & 31, wid = t >> 5;
    int warp_m = (wid & 1) * 64, warp_n = (wid >> 1) * 32;
    int q = lane & 3, g = lane >> 2;
    bool dodiag = (blockIdx.x == 0);

    if (t < 128) diagacc[t] = 0.f;
    __syncthreads();

    #pragma unroll
    for (int j = 0; j < 8; j++) {
        int i = t + j * 256;
        int row = i >> 4, c = (i & 15) * 4;
        float4 v = *(const float4*)&X[(size_t)(n0 + row) * DIM + h * DH + c];
        *(__half2*)&As[row * FSH + c] = __floats2half2_rn(v.x, v.y);
        *(__half2*)&As[row * FSH + c + 2] = __floats2half2_rn(v.z, v.w);
        if (dodiag)
            atomicAdd(&diagacc[row], v.x * v.x + v.y * v.y + v.z * v.z + v.w * v.w);
    }
    #pragma unroll
    for (int j = 0; j < 8; j++) {
        int i = t + j * 256;
        int m = i >> 4, d = (i & 15) * 4;
        float4 v = *(const float4*)&proj[(size_t)(m0 + m) * DH + d];
        *(__half2*)&Bs[m * FSH + d] = __floats2half2_rn(v.x * DNORM, v.y * DNORM);
        *(__half2*)&Bs[m * FSH + d + 2] = __floats2half2_rn(v.z * DNORM, v.w * DNORM);
    }
    __syncthreads();

    float acc[4][4][4];
    #pragma unroll
    for (int mt = 0; mt < 4; mt++)
        #pragma unroll
        for (int nt = 0; nt < 4; nt++)
            #pragma unroll
            for (int e = 0; e < 4; e++) acc[mt][nt][e] = 0.f;

    const uint32_t* asw = (const uint32_t*)As;
    const uint32_t* bsw = (const uint32_t*)Bs;
    #pragma unroll
    for (int ks = 0; ks < 4; ks++) {
        int k0w = ks * 8;
        uint32_t af[4][4], bf[4][2];
        #pragma unroll
        for (int mt = 0; mt < 4; mt++) {
            int m = warp_m + mt * 16 + g;
            af[mt][0] = asw[m * 36 + k0w + q];
            af[mt][1] = asw[(m + 8) * 36 + k0w + q];
            af[mt][2] = asw[m * 36 + k0w + q + 4];
            af[mt][3] = asw[(m + 8) * 36 + k0w + q + 4];
        }
        #pragma unroll
        for (int nt = 0; nt < 4; nt++) {
            int n = warp_n + nt * 8 + g;
            bf[nt][0] = bsw[n * 36 + k0w + q];
            bf[nt][1] = bsw[n * 36 + k0w + q + 4];
        }
        #pragma unroll
        for (int mt = 0; mt < 4; mt++)
            #pragma unroll
            for (int nt = 0; nt < 4; nt++)
                mma16(acc[mt][nt], af[mt], bf[nt]);
    }

    if (dodiag && t < 128) {
        float* dg = isK ? g_diagk : g_diagq;
        dg[h * NTOK + n0 + t] = 0.5f * (DNORM * DNORM) * diagacc[t];
    }

    #pragma unroll
    for (int mt = 0; mt < 4; mt++)
        #pragma unroll
        for (int nt = 0; nt < 4; nt++)
            #pragma unroll
            for (int eh = 0; eh < 2; eh++) {
                int row = warp_m + mt * 16 + g + eh * 8;
                int col = warp_n + nt * 8 + q * 2;
                *(__half2*)&dst[((size_t)h * NTOK + n0 + row) * MF + m0 + col] =
                    __floats2half2_rn(acc[mt][nt][eh * 2], acc[mt][nt][eh * 2 + 1]);
            }

    if (!isK) {
        #pragma unroll
        for (int mt = 0; mt < 4; mt++)
            #pragma unroll
            for (int eh = 0; eh < 2; eh++) {
                float v = -1e30f;
                #pragma unroll
                for (int nt = 0; nt < 4; nt++) {
                    v = fmaxf(v, acc[mt][nt][eh * 2]);
                    v = fmaxf(v, acc[mt][nt][eh * 2 + 1]);
                }
                v = fmaxf(v, __shfl_xor_sync(0xffffffffu, v, 1));
                v = fmaxf(v, __shfl_xor_sync(0xffffffffu, v, 2));
                if (q == 0)
                    redq[wid >> 1][warp_m + mt * 16 + g + eh * 8] = v;
            }
        __syncthreads();
        if (t < 128) {
            float v = fmaxf(fmaxf(redq[0][t], redq[1][t]), fmaxf(redq[2][t], redq[3][t]));
            g_maxq2[(size_t)blockIdx.x * HEADS * NTOK + h * NTOK + n0 + t] = v;
        }
    } else {
        float v = -1e30f;
        #pragma unroll
        for (int mt = 0; mt < 4; mt++)
            #pragma unroll
            for (int nt = 0; nt < 4; nt++)
                #pragma unroll
                for (int e = 0; e < 4; e++) v = fmaxf(v, acc[mt][nt][e]);
        for (int off = 16; off; off >>= 1) v = fmaxf(v, __shfl_xor_sync(0xffffffffu, v, off));
        if (lane == 0) wred[wid] = v;
        __syncthreads();
        if (t == 0) {
            float mx = wred[0];
            #pragma unroll
            for (int w = 1; w < 8; w++) mx = fmaxf(mx, wred[w]);
            g_maxk2[h * 64 + blockIdx.y * 2 + blockIdx.x] = mx;
        }
    }
}

// ---------------- ctx GEMM (tf32, NZS partials, fast exp, half kf) --------
#define CSA 136
#define CSB 72
__global__ __launch_bounds__(256) void ctxgemm_kernel(const float* __restrict__ methy) {
    __shared__ float As[32 * CSA];
    __shared__ float Bs[32 * CSB];
    __shared__ float mkred[64];
    int h = blockIdx.x, m0 = blockIdx.y * 128, zs = blockIdx.z;
    int nbase = zs * (NTOK / NZS);
    int t = threadIdx.x, lane = t & 31, wid = t >> 5;
    int warp_m = (wid & 3) * 32, warp_n = (wid >> 2) * 32;
    int q = lane & 3, g = lane >> 2;

    if (t < 64) mkred[t] = g_maxk2[h * 64 + t];
    __syncthreads();
    float mk = mkred[0];
    #pragma unroll
    for (int i = 1; i < 64; i++) mk = fmaxf(mk, mkred[i]);

    int sr = t >> 3;
    int sc = (t & 7) * 4;

    float acc[2][4][4];
    #pragma unroll
    for (int mt = 0; mt < 2; mt++)
        #pragma unroll
        for (int nt = 0; nt < 4; nt++)
            #pragma unroll
            for (int e = 0; e < 4; e++) acc[mt][nt][e] = 0.f;
    float ksacc[16];
    #pragma unroll
    for (int i = 0; i < 16; i++) ksacc[i] = 0.f;

    for (int c = 0; c < NTOK / NZS; c += 32) {
        int n = nbase + c + sr;
        float cc = (g_diagk[h * NTOK + n] + mk) * L2E;
        float msk = (methy[n] != 0.0f) ? RATIO : 0.0f;
        const __half* src = &g_kf[((size_t)h * NTOK + n) * MF + m0];
        #pragma unroll
        for (int j = 0; j < 4; j++) {
            int col = sc + 32 * j;
            float2 f0 = __half22float2(*(const __half2*)&src[col]);
            float2 f1 = __half22float2(*(const __half2*)&src[col + 2]);
            float4 w;
            w.x = (ex2f(fmaf(f0.x, L2E, -cc)) + 1e-4f) * msk;
            w.y = (ex2f(fmaf(f0.y, L2E, -cc)) + 1e-4f) * msk;
            w.z = (ex2f(fmaf(f1.x, L2E, -cc)) + 1e-4f) * msk;
            w.w = (ex2f(fmaf(f1.y, L2E, -cc)) + 1e-4f) * msk;
            *(float4*)&As[sr * CSA + col] = w;
            ksacc[j * 4 + 0] += w.x; ksacc[j * 4 + 1] += w.y;
            ksacc[j * 4 + 2] += w.z; ksacc[j * 4 + 3] += w.w;
        }
        #pragma unroll
        for (int j = 0; j < 2; j++) {
            int fi = t * 2 + j;
            int row = fi >> 4, col = (fi & 15) * 4;
            *(float4*)&Bs[row * CSB + col] =
                *(const float4*)&g_v[(size_t)(nbase + c + row) * DIM + h * DH + col];
        }
        __syncthreads();
        #pragma unroll
        for (int kk = 0; kk < 4; kk++) {
            int k = kk * 8;
            uint32_t af[2][4], bf[4][2];
            #pragma unroll
            for (int mt = 0; mt < 2; mt++) {
                int m = warp_m + mt * 16 + g;
                af[mt][0] = to_tf32u(As[(k + q) * CSA + m]);
                af[mt][1] = to_tf32u(As[(k + q) * CSA + m + 8]);
                af[mt][2] = to_tf32u(As[(k + 4 + q) * CSA + m]);
                af[mt][3] = to_tf32u(As[(k + 4 + q) * CSA + m + 8]);
            }
            #pragma unroll
            for (int nt = 0; nt < 4; nt++) {
                int n2 = warp_n + nt * 8 + g;
                bf[nt][0] = to_tf32u(Bs[(k + q) * CSB + n2]);
                bf[nt][1] = to_tf32u(Bs[(k + 4 + q) * CSB + n2]);
            }
            #pragma unroll
            for (int mt = 0; mt < 2; mt++)
                #pragma unroll
                for (int nt = 0; nt < 4; nt++)
                    mma8(acc[mt][nt], af[mt], bf[nt]);
        }
        __syncthreads();
    }

    #pragma unroll
    for (int j = 0; j < 4; j++) {
        int col = sc + 32 * j;
        *(float4*)&As[sr * CSA + col] = make_float4(ksacc[j*4], ksacc[j*4+1], ksacc[j*4+2], ksacc[j*4+3]);
    }
    __syncthreads();
    if (t < 128) {
        float s = 0.f;
        #pragma unroll
        for (int r = 0; r < 32; r++) s += As[r * CSA + t];
        g_ksump[((size_t)zs * HEADS + h) * MF + m0 + t] = s;
    }
    float* ctxp = &g_ctxp[((size_t)zs * HEADS + h) * MF * DH];
    #pragma unroll
    for (int mt = 0; mt < 2; mt++)
        #pragma unroll
        for (int nt = 0; nt < 4; nt++)
            #pragma unroll
            for (int e = 0; e < 4; e++) {
                int m = m0 + warp_m + mt * 16 + g + (e >> 1) * 8;
                int d = warp_n + nt * 8 + q * 2 + (e & 1);
                ctxp[(size_t)m * DH + d] = acc[mt][nt][e];
            }
}

// ---------------- reduce partials ----------------
__global__ __launch_bounds__(256) void reduce_kernel() {
    int i = blockIdx.x * 256 + threadIdx.x;
    int nt = gridDim.x * 256;
    for (int j = i; j < HEADS * MF * DH; j += nt) {
        float s = 0.f;
        #pragma unroll
        for (int z = 0; z < NZS; z++) s += g_ctxp[(size_t)z * HEADS * MF * DH + j];
        g_ctx[j] = s;
    }
    for (int j = i; j < HEADS * MF; j += nt) {
        float s = 0.f;
        #pragma unroll
        for (int z = 0; z < NZS; z++) s += g_ksump[(size_t)z * HEADS * MF + j];
        g_ksum[j] = s;
    }
}

// ---------------- attn GEMM fp16 (half qf in), half output ----------------
#define ATS 40   /* halves stride = 20 words */
__global__ __launch_bounds__(256) void attngemm_kernel() {
    __shared__ __half As[128 * ATS];
    __shared__ __half Bs[64 * ATS];
    __shared__ float ksums[MF];
    __shared__ float dens[128];
    int h = blockIdx.x, n0 = blockIdx.y * 128;
    int t = threadIdx.x, lane = t & 31, wid = t >> 5;
    int warp_m = (wid & 3) * 32, warp_n = (wid >> 2) * 32;
    int q = lane & 3, g = lane >> 2;

    ksums[t] = g_ksum[h * MF + t];
    __syncthreads();

    int sr = t >> 1;
    int n = n0 + sr;
    float mq = fmaxf(g_maxq2[h * NTOK + n], g_maxq2[(size_t)HEADS * NTOK + h * NTOK + n]);
    float cc = (g_diagq[h * NTOK + n] + mq) * L2E;
    float denp = 0.f;

    float acc[2][4][4];
    #pragma unroll
    for (int mt = 0; mt < 2; mt++)
        #pragma unroll
        for (int nt = 0; nt < 4; nt++)
            #pragma unroll
            for (int e = 0; e < 4; e++) acc[mt][nt][e] = 0.f;

    for (int c = 0; c < 256; c += 32) {
        const __half* src = &g_qf[((size_t)h * NTOK + n) * MF + c];
        #pragma unroll
        for (int j = 0; j < 4; j++) {
            int col = ((t & 1) * 4 + j) * 4;
            float2 f0 = __half22float2(*(const __half2*)&src[col]);
            float2 f1 = __half22float2(*(const __half2*)&src[col + 2]);
            float4 w;
            w.x = RATIO * (ex2f(fmaf(f0.x, L2E, -cc)) + 1e-4f);
            w.y = RATIO * (ex2f(fmaf(f0.y, L2E, -cc)) + 1e-4f);
            w.z = RATIO * (ex2f(fmaf(f1.x, L2E, -cc)) + 1e-4f);
            w.w = RATIO * (ex2f(fmaf(f1.y, L2E, -cc)) + 1e-4f);
            *(__half2*)&As[sr * ATS + col] = __floats2half2_rn(w.x, w.y);
            *(__half2*)&As[sr * ATS + col + 2] = __floats2half2_rn(w.z, w.w);
            denp += w.x * ksums[c + col] + w.y * ksums[c + col + 1]
                  + w.z * ksums[c + col + 2] + w.w * ksums[c + col + 3];
        }
        #pragma unroll
        for (int j = 0; j < 2; j++) {
            int fi = t * 2 + j;
            int row = fi >> 4, col4 = (fi & 15) * 4;
            float4 v = *(const float4*)&g_ctx[(size_t)h * MF * DH + (size_t)(c + row) * DH + col4];
            Bs[(col4 + 0) * ATS + row] = __float2half(v.x);
            Bs[(col4 + 1) * ATS + row] = __float2half(v.y);
            Bs[(col4 + 2) * ATS + row] = __float2half(v.z);
            Bs[(col4 + 3) * ATS + row] = __float2half(v.w);
        }
        __syncthreads();
        const uint32_t* aw = (const uint32_t*)As;
        const uint32_t* bw = (const uint32_t*)Bs;
        #pragma unroll
        for (int ks = 0; ks < 2; ks++) {
            uint32_t af[2][4], bf[4][2];
            #pragma unroll
            for (int mt = 0; mt < 2; mt++) {
                int m = warp_m + mt * 16 + g;
                af[mt][0] = aw[m * 20 + ks * 8 + q];
                af[mt][1] = aw[(m + 8) * 20 + ks * 8 + q];
                af[mt][2] = aw[m * 20 + ks * 8 + q + 4];
                af[mt][3] = aw[(m + 8) * 20 + ks * 8 + q + 4];
            }
            #pragma unroll
            for (int nt = 0; nt < 4; nt++) {
                int d = warp_n + nt * 8 + g;
                bf[nt][0] = bw[d * 20 + ks * 8 + q];
                bf[nt][1] = bw[d * 20 + ks * 8 + q + 4];
            }
            #pragma unroll
            for (int mt = 0; mt < 2; mt++)
                #pragma unroll
                for (int nt = 0; nt < 4; nt++)
                    mma16(acc[mt][nt], af[mt], bf[nt]);
        }
        __syncthreads();
    }

    denp += __shfl_xor_sync(0xffffffffu, denp, 1);
    if ((t & 1) == 0) dens[sr] = denp;
    __syncthreads();

    #pragma unroll
    for (int mt = 0; mt < 2; mt++)
        #pragma unroll
        for (int nt = 0; nt < 4; nt++)
            #pragma unroll
            for (int e = 0; e < 4; e++) {
                int row = warp_m + mt * 16 + g + (e >> 1) * 8;
                int d = warp_n + nt * 8 + q * 2 + (e & 1);
                g_attnh[(size_t)(n0 + row) * DIM + h * DH + d] =
                    __float2half(acc[mt][nt][e] / dens[row]);
            }
}

// ---------------- host ----------------
extern "C" void kernel_launch(void* const* d_in, const int* in_sizes, int n_in,
                              void* d_out, int out_size) {
    const float* methy = (const float*)d_in[0];
    const int* chromo = (const int*)d_in[1];
    const int* pos    = (const int*)d_in[2];
    const float* mt = (const float*)d_in[3];
    const float* ct = (const float*)d_in[4];
    const float* pt = (const float*)d_in[5];
    const float* ln1g = (const float*)d_in[6];
    const float* ln1b = (const float*)d_in[7];
    const float* ln2g = (const float*)d_in[8];
    const float* ln2b = (const float*)d_in[9];
    const float* Wq = (const float*)d_in[10];
    const float* Wk = (const float*)d_in[11];
    const float* Wv = (const float*)d_in[12];
    const float* Wo = (const float*)d_in[13];
    const float* bo = (const float*)d_in[14];
    const float* W1 = (const float*)d_in[15];
    const float* b1 = (const float*)d_in[16];
    const float* W2 = (const float*)d_in[17];
    const float* b2 = (const float*)d_in[18];
    const float* proj = (const float*)d_in[19];
    const float* nfg = (const float*)d_in[20];
    const float* nfb = (const float*)d_in[21];
    const float* Wout = (const float*)d_in[22];
    const float* bout = (const float*)d_in[23];
    float* out = (float*)d_out;

    float *px, *pq, *pk, *pv;
    __half *phh, *pattnh, *pffh, *pwh;
    cudaGetSymbolAddress((void**)&px, g_x);
    cudaGetSymbolAddress((void**)&phh, g_hh);
    cudaGetSymbolAddress((void**)&pq, g_q);
    cudaGetSymbolAddress((void**)&pk, g_k);
    cudaGetSymbolAddress((void**)&pv, g_v);
    cudaGetSymbolAddress((void**)&pattnh, g_attnh);
    cudaGetSymbolAddress((void**)&pffh, g_ffh);
    cudaGetSymbolAddress((void**)&pwh, g_wh);

    const int GEMMH_SMEM = HSTAGES * 2 * HAELE * 2;                  // 110,592
    cudaFuncSetAttribute(tgemm_h, cudaFuncAttributeMaxDynamicSharedMemorySize, GEMMH_SMEM);
    cudaFuncSetAttribute(woutgemm_kernel, cudaFuncAttributeMaxDynamicSharedMemorySize, GEMMH_SMEM);

    wconv_sq<<<dim3(24, 24, DEPTH * 4), 256>>>(Wq, Wk, Wv, Wo);
    wconv_ff<<<dim3(2304, DEPTH, 2), 256>>>(W1, W2);
    wconv_out<<<(128 * DIM + 255) / 256, 256>>>(Wout);
    embed_kernel<<<NTOK, 256>>>(methy, chromo, pos, mt, ct, pt);

    dim3 gqkv(DIM / 128, NTOK / 128, 3);
    dim3 gsk3(DIM / 128, NTOK / 128, 3);
    dim3 gff(FF / 128, NTOK / 128, 1);
    dim3 gfeat(2, 32, HEADS * 2);
    dim3 gctx(HEADS, 2, NZS);
    dim3 gattn(HEADS, NTOK / 128);

    for (int l = 0; l < DEPTH; l++) {
        const float* pj = proj + (size_t)l * MF * DH;
        const __half* wl = pwh + (size_t)l * LOFF;
        // --- attention ---
        ln_kernel<<<NTOK / 2, 384>>>(px, ln1g + l * DIM, ln1b + l * DIM, phh);
        tgemm_h<<<gqkv, 256, GEMMH_SMEM>>>(phh,
            wl + WOQ, wl + WOK, wl + WOV,
            nullptr, pq, pk, pv, DIM, DIM, 0, 1, 0);
        featgemm_kernel<<<gfeat, 256>>>(pj);
        ctxgemm_kernel<<<gctx, 256>>>(methy);
        reduce_kernel<<<192, 256>>>();
        attngemm_kernel<<<gattn, 256>>>();
        tgemm_h<<<gsk3, 256, GEMMH_SMEM>>>(pattnh,
            wl + WOO, nullptr, nullptr,
            bo + l * DIM, px, nullptr, nullptr, DIM, DIM, 0, 3, 0);
        // --- FFN ---
        ln_kernel<<<NTOK / 2, 384>>>(px, ln2g + l * DIM, ln2b + l * DIM, phh);
        tgemm_h<<<gff, 256, GEMMH_SMEM>>>(phh,
            wl + WO1, nullptr, nullptr,
            b1 + l * FF, (float*)pffh, nullptr, nullptr, FF, DIM, 1, 1, 1);
        tgemm_h<<<gsk3, 256, GEMMH_SMEM>>>(pffh,
            wl + WO2, nullptr, nullptr,
            b2 + l * DIM, px, nullptr, nullptr, DIM, FF, 0, 3, 0);
    }

    ln_kernel<<<NTOK / 2, 384>>>(px, nfg, nfb, phh);
    woutgemm_kernel<<<NTOK / 128, 256, GEMMH_SMEM>>>(phh, bout, out);
}